// round 8
// baseline (speedup 1.0000x reference)
#include <cuda_runtime.h>
#include <math.h>
#include <stdint.h>

#define B_  2
#define L_  2048
#define D_  1024
#define H_  16
#define HD_ 64
#define M_  (B_*L_)   // 4096

// Scratch (device globals — no allocation allowed)
__device__ float g_q[B_*H_*L_*HD_];
__device__ float g_k[B_*H_*L_*HD_];
__device__ float g_v[B_*H_*L_*HD_];
__device__ float g_ctx[B_*L_*D_];

// ---------------------------------------------------------------------------
// helpers
// ---------------------------------------------------------------------------
__device__ __forceinline__ uint32_t f2tf(float f) {
    uint32_t r;
    asm("cvt.rna.tf32.f32 %0, %1;" : "=r"(r) : "f"(f));
    return r;
}
__device__ __forceinline__ uint32_t smem_u32(const void* p) {
    uint32_t a;
    asm("{ .reg .u64 t; cvta.to.shared.u64 t, %1; cvt.u32.u64 %0, t; }"
        : "=r"(a) : "l"(p));
    return a;
}
__device__ __forceinline__ void cp16(uint32_t s, const void* g) {
    asm volatile("cp.async.cg.shared.global [%0], [%1], 16;" :: "r"(s), "l"(g));
}
// D += A*B, m16n8k8 tf32 (A row-major, B col-major)
__device__ __forceinline__ void mma8(float* d, const uint32_t* a, const uint32_t* b) {
    asm volatile(
        "mma.sync.aligned.m16n8k8.row.col.f32.tf32.tf32.f32 "
        "{%0,%1,%2,%3}, {%4,%5,%6,%7}, {%8,%9}, {%0,%1,%2,%3};"
        : "+f"(d[0]), "+f"(d[1]), "+f"(d[2]), "+f"(d[3])
        : "r"(a[0]), "r"(a[1]), "r"(a[2]), "r"(a[3]), "r"(b[0]), "r"(b[1]));
}
// 4x (8x8 b16) ldmatrix
__device__ __forceinline__ void ldm4(uint32_t* r, uint32_t a) {
    asm volatile("ldmatrix.sync.aligned.m8n8.x4.shared.b16 {%0,%1,%2,%3}, [%4];"
                 : "=r"(r[0]), "=r"(r[1]), "=r"(r[2]), "=r"(r[3]) : "r"(a));
}

// ===========================================================================
// GEMM body: C[M,N] = X[M,K] @ W[N,K]^T (+bias), K=N=1024.
// 128x128 CTA tile, 256 thr (8 warps 2x4), warp tile 64x32, K-chunk 32.
// cp.async double-buffered raw-fp32 smem; ldmatrix fragment loads; cvt after.
// ===========================================================================
#define GST (128 * 36)           // words per operand per stage
#define GEMM_SMEM (4 * GST * 4)  // 2 stages x (A+B) = 73728 bytes

template<bool SPLIT, bool BIAS>
__device__ __forceinline__ void gemm_body(const float* __restrict__ X,
                                          const float* __restrict__ W,
                                          const float* __restrict__ bias,
                                          float* __restrict__ out,
                                          uint32_t* dsm,
                                          int m0, int n0)
{
    const int tid  = threadIdx.x;
    const int wid  = tid >> 5, lane = tid & 31;
    const int qd   = lane & 3, gr = lane >> 2;
    const int wm   = wid >> 2, wn = wid & 3;

    float acc[4][4][4];
    #pragma unroll
    for (int a = 0; a < 4; a++)
        #pragma unroll
        for (int b = 0; b < 4; b++)
            #pragma unroll
            for (int c = 0; c < 4; c++) acc[a][b][c] = 0.f;

    const int lrow = tid >> 1;            // 0..127
    const int lcol = (tid & 1) * 16;      // 0 / 16
    const float* Xp = X + (size_t)(m0 + lrow) * D_ + lcol;
    const float* Wp = W + (size_t)(n0 + lrow) * D_ + lcol;
    const uint32_t sAb0 = smem_u32(dsm + lrow * 36 + lcol);

    // ldmatrix lane addressing (derivation in round notes):
    // A x4 tiles: (rows0-7,k0-3)(rows8-15,k0-3)(rows0-7,k4-7)(rows8-15,k4-7)
    const int a_r = ((lane >> 3) & 1) * 8 + (lane & 7);
    const int a_c = (lane >> 4) * 4;
    // B x4 tiles: (nt rows0-7,k0-3)(same,k4-7)(nt+1 rows,k0-3)(nt+1,k4-7)
    const int b_r = (lane >> 4) * 8 + (lane & 7);
    const int b_c = ((lane >> 3) & 1) * 4;
    const uint32_t sbase  = smem_u32(dsm);
    const uint32_t aAddr0 = sbase + (((wm * 64 + a_r) * 36 + a_c) << 2);
    const uint32_t bAddr0 = sbase + (GST << 2) + (((wn * 32 + b_r) * 36 + b_c) << 2);

    auto issue = [&](int c, int st) {
        const uint32_t sa = sAb0 + st * (2 * GST * 4);
        const uint32_t sb = sa + GST * 4;
        #pragma unroll
        for (int u = 0; u < 4; u++) {
            cp16(sa + u * 16, Xp + c + u * 4);
            cp16(sb + u * 16, Wp + c + u * 4);
        }
        asm volatile("cp.async.commit_group;");
    };

    issue(0, 0);

    for (int c = 0, st = 0; c < D_; c += 32, st ^= 1) {
        if (c + 32 < D_) {
            issue(c + 32, st ^ 1);
            asm volatile("cp.async.wait_group 1;");
        } else {
            asm volatile("cp.async.wait_group 0;");
        }
        __syncthreads();

        const uint32_t soff = (uint32_t)st * (2 * GST * 4);
        #pragma unroll
        for (int kk = 0; kk < 32; kk += 8) {
            uint32_t af[4][4], bq[2][4];
            #pragma unroll
            for (int mt = 0; mt < 4; mt++)
                ldm4(af[mt], aAddr0 + soff + ((mt * 16 * 36 + kk) << 2));
            #pragma unroll
            for (int ntp = 0; ntp < 2; ntp++)
                ldm4(bq[ntp], bAddr0 + soff + ((ntp * 16 * 36 + kk) << 2));
            #pragma unroll
            for (int mt = 0; mt < 4; mt++)
                #pragma unroll
                for (int i = 0; i < 4; i++)
                    af[mt][i] = f2tf(__uint_as_float(af[mt][i]));
            #pragma unroll
            for (int ntp = 0; ntp < 2; ntp++)
                #pragma unroll
                for (int i = 0; i < 4; i++)
                    bq[ntp][i] = f2tf(__uint_as_float(bq[ntp][i]));
            #pragma unroll
            for (int mt = 0; mt < 4; mt++)
                #pragma unroll
                for (int nt = 0; nt < 4; nt++)
                    mma8(acc[mt][nt], af[mt], &bq[nt >> 1][(nt & 1) * 2]);
        }
        __syncthreads();
    }

    #pragma unroll
    for (int mt = 0; mt < 4; mt++) {
        #pragma unroll
        for (int half = 0; half < 2; half++) {
            const int m = m0 + wm * 64 + mt * 16 + gr + half * 8;
            #pragma unroll
            for (int nt = 0; nt < 4; nt++) {
                const int n = n0 + wn * 32 + nt * 8 + qd * 2;
                float2 v;
                v.x = acc[mt][nt][half * 2 + 0];
                v.y = acc[mt][nt][half * 2 + 1];
                if (BIAS) { v.x += bias[n]; v.y += bias[n + 1]; }
                if (SPLIT) {
                    const int b = m / L_, l = m % L_, h = n / HD_, d = n % HD_;
                    *(float2*)&out[(((size_t)(b * H_ + h)) * L_ + l) * HD_ + d] = v;
                } else {
                    *(float2*)&out[(size_t)m * D_ + n] = v;
                }
            }
        }
    }
}

// Merged Q/K/V projection: blockIdx.z selects the problem.
__global__ __launch_bounds__(256, 2) void gemm_qkv(const float* __restrict__ q,
                                                   const float* __restrict__ k,
                                                   const float* __restrict__ v,
                                                   const float* __restrict__ Wq,
                                                   const float* __restrict__ Wk,
                                                   const float* __restrict__ Wv,
                                                   float* __restrict__ oq,
                                                   float* __restrict__ ok,
                                                   float* __restrict__ ov)
{
    extern __shared__ uint32_t dsm[];
    const float *X, *W;
    float* out;
    if (blockIdx.z == 0)      { X = q; W = Wq; out = oq; }
    else if (blockIdx.z == 1) { X = k; W = Wk; out = ok; }
    else                      { X = v; W = Wv; out = ov; }
    gemm_body<true, false>(X, W, nullptr, out, dsm,
                           blockIdx.y * 128, blockIdx.x * 128);
}

__global__ __launch_bounds__(256, 2) void gemm_out(const float* __restrict__ X,
                                                   const float* __restrict__ W,
                                                   const float* __restrict__ bias,
                                                   float* __restrict__ out)
{
    extern __shared__ uint32_t dsm[];
    gemm_body<false, true>(X, W, bias, out, dsm,
                           blockIdx.y * 128, blockIdx.x * 128);
}

// ===========================================================================
// Flash attention, FA2-style: q-tile 128, 4 warps, warp tile 32 rows x 64 keys
// (mt=2 -> K/V smem traffic per mma halved vs 8x16). ldmatrix for Q/K frags.
// smem: Qs 128x68 (tf32, pre-scaled), Ks 64x68, Vs 64x72, msk 64.
// ===========================================================================
#define FQS 0
#define FKS (128 * 68)
#define FVS (FKS + 64 * 68)
#define FMK (FVS + 64 * 72)
#define FA_SMEM ((FMK + 64) * 4)   // 70912 bytes

__global__ __launch_bounds__(128, 2) void flash_attn(const float* __restrict__ q,
                                                     const float* __restrict__ k,
                                                     const float* __restrict__ v,
                                                     const int*   __restrict__ mask,
                                                     float* __restrict__ ctx)
{
    extern __shared__ uint32_t smu[];
    uint32_t* Qs  = smu + FQS;
    uint32_t* Ks  = smu + FKS;
    uint32_t* Vs  = smu + FVS;
    int*      msk = (int*)(smu + FMK);

    const int bh = blockIdx.x;
    const int b  = bh / H_;
    const int h  = bh % H_;
    const int q0 = blockIdx.y * 128;
    const int tid  = threadIdx.x;
    const int wid  = tid >> 5, lane = tid & 31;
    const int qd   = lane & 3, gr = lane >> 2;

    const float* qbase = q + (size_t)bh * L_ * HD_;
    const float* kbase = k + (size_t)bh * L_ * HD_;
    const float* vbase = v + (size_t)bh * L_ * HD_;

    // Load Q tile 128x64 (scaled by 1/8, tf32): thread owns one row
    {
        const float* src = qbase + (size_t)(q0 + tid) * HD_;
        uint32_t* dst = Qs + tid * 68;
        #pragma unroll
        for (int u = 0; u < 16; u++) {
            const float4 qv = *(const float4*)(src + u * 4);
            uint4 t;
            t.x = f2tf(qv.x * 0.125f); t.y = f2tf(qv.y * 0.125f);
            t.z = f2tf(qv.z * 0.125f); t.w = f2tf(qv.w * 0.125f);
            *(uint4*)(dst + u * 4) = t;
        }
    }

    float accO[2][8][4];
    #pragma unroll
    for (int mt = 0; mt < 2; mt++)
        #pragma unroll
        for (int a = 0; a < 8; a++)
            #pragma unroll
            for (int c = 0; c < 4; c++) accO[mt][a][c] = 0.f;
    float m_r[2][2] = {{-1e30f, -1e30f}, {-1e30f, -1e30f}};
    float l_r[2][2] = {{0.f, 0.f}, {0.f, 0.f}};

    // ldmatrix lane addressing
    const int a_r = ((lane >> 3) & 1) * 8 + (lane & 7);
    const int a_c = (lane >> 4) * 4;
    const int k_r = (lane >> 4) * 8 + (lane & 7);
    const int k_c = ((lane >> 3) & 1) * 4;
    const uint32_t qAddr = smem_u32(Qs + (wid * 32 + a_r) * 68 + a_c);
    const uint32_t kAddr = smem_u32(Ks + k_r * 68 + k_c);

    const int srcA = (lane & ~3) | (qd >> 1);
    const int srcB = srcA + 2;
    const bool odd = (qd & 1);

    __syncthreads();

    for (int k0 = 0; k0 < L_; k0 += 64) {
        // Load K (stride 68) and V (stride 72) tiles, tf32
        {
            const int rr = tid >> 1, hc = (tid & 1) * 32;
            const float* ks = kbase + (size_t)(k0 + rr) * HD_ + hc;
            const float* vs = vbase + (size_t)(k0 + rr) * HD_ + hc;
            uint32_t* kd = Ks + rr * 68 + hc;
            uint32_t* vd = Vs + rr * 72 + hc;
            #pragma unroll
            for (int u = 0; u < 8; u++) {
                const float4 kv = *(const float4*)(ks + u * 4);
                const float4 vv = *(const float4*)(vs + u * 4);
                uint4 tk, tv;
                tk.x = f2tf(kv.x); tk.y = f2tf(kv.y); tk.z = f2tf(kv.z); tk.w = f2tf(kv.w);
                tv.x = f2tf(vv.x); tv.y = f2tf(vv.y); tv.z = f2tf(vv.z); tv.w = f2tf(vv.w);
                *(uint4*)(kd + u * 4) = tk;
                *(uint4*)(vd + u * 4) = tv;
            }
        }
        if (tid < 64) msk[tid] = mask[b * L_ + k0 + tid];
        __syncthreads();

        // ---- S = Q*K^T (scale folded into Q); warp covers 32 rows x 64 keys
        float sacc[2][8][4];
        #pragma unroll
        for (int mt = 0; mt < 2; mt++)
            #pragma unroll
            for (int a = 0; a < 8; a++)
                #pragma unroll
                for (int c = 0; c < 4; c++) sacc[mt][a][c] = 0.f;

        #pragma unroll
        for (int g = 0; g < 8; g++) {
            uint32_t aq[2][4], kb[4][4];
            ldm4(aq[0], qAddr + ((g * 8) << 2));
            ldm4(aq[1], qAddr + ((16 * 68 + g * 8) << 2));
            #pragma unroll
            for (int ntp = 0; ntp < 4; ntp++)
                ldm4(kb[ntp], kAddr + ((ntp * 16 * 68 + g * 8) << 2));
            #pragma unroll
            for (int mt = 0; mt < 2; mt++)
                #pragma unroll
                for (int nt = 0; nt < 8; nt++)
                    mma8(sacc[mt][nt], aq[mt], &kb[nt >> 1][(nt & 1) * 2]);
        }

        // ---- mask + online softmax, fully in registers (per mt)
        #pragma unroll
        for (int mt = 0; mt < 2; mt++) {
            #pragma unroll
            for (int nt = 0; nt < 8; nt++) {
                if (!msk[8 * nt + 2 * qd])     { sacc[mt][nt][0] = -1e30f; sacc[mt][nt][2] = -1e30f; }
                if (!msk[8 * nt + 2 * qd + 1]) { sacc[mt][nt][1] = -1e30f; sacc[mt][nt][3] = -1e30f; }
            }
            float rm0 = m_r[mt][0], rm1 = m_r[mt][1];
            #pragma unroll
            for (int nt = 0; nt < 8; nt++) {
                rm0 = fmaxf(rm0, fmaxf(sacc[mt][nt][0], sacc[mt][nt][1]));
                rm1 = fmaxf(rm1, fmaxf(sacc[mt][nt][2], sacc[mt][nt][3]));
            }
            rm0 = fmaxf(rm0, __shfl_xor_sync(0xFFFFFFFF, rm0, 1));
            rm0 = fmaxf(rm0, __shfl_xor_sync(0xFFFFFFFF, rm0, 2));
            rm1 = fmaxf(rm1, __shfl_xor_sync(0xFFFFFFFF, rm1, 1));
            rm1 = fmaxf(rm1, __shfl_xor_sync(0xFFFFFFFF, rm1, 2));

            const float corr0 = __expf(m_r[mt][0] - rm0);
            const float corr1 = __expf(m_r[mt][1] - rm1);
            float ls0 = 0.f, ls1 = 0.f;
            #pragma unroll
            for (int nt = 0; nt < 8; nt++) {
                sacc[mt][nt][0] = (sacc[mt][nt][0] < -1e29f) ? 0.f : __expf(sacc[mt][nt][0] - rm0);
                sacc[mt][nt][1] = (sacc[mt][nt][1] < -1e29f) ? 0.f : __expf(sacc[mt][nt][1] - rm0);
                sacc[mt][nt][2] = (sacc[mt][nt][2] < -1e29f) ? 0.f : __expf(sacc[mt][nt][2] - rm1);
                sacc[mt][nt][3] = (sacc[mt][nt][3] < -1e29f) ? 0.f : __expf(sacc[mt][nt][3] - rm1);
                ls0 += sacc[mt][nt][0] + sacc[mt][nt][1];
                ls1 += sacc[mt][nt][2] + sacc[mt][nt][3];
            }
            ls0 += __shfl_xor_sync(0xFFFFFFFF, ls0, 1);
            ls0 += __shfl_xor_sync(0xFFFFFFFF, ls0, 2);
            ls1 += __shfl_xor_sync(0xFFFFFFFF, ls1, 1);
            ls1 += __shfl_xor_sync(0xFFFFFFFF, ls1, 2);

            m_r[mt][0] = rm0; m_r[mt][1] = rm1;
            l_r[mt][0] = l_r[mt][0] * corr0 + ls0;
            l_r[mt][1] = l_r[mt][1] * corr1 + ls1;

            #pragma unroll
            for (int nt = 0; nt < 8; nt++) {
                accO[mt][nt][0] *= corr0; accO[mt][nt][1] *= corr0;
                accO[mt][nt][2] *= corr1; accO[mt][nt][3] *= corr1;
            }
        }

        // ---- P (C-frag) -> A-frag via quad shuffles, then O += P @ V
        #pragma unroll
        for (int g = 0; g < 8; g++) {
            uint32_t vb[8][2];
            #pragma unroll
            for (int nt = 0; nt < 8; nt++) {
                const uint32_t* vp = Vs + (g * 8 + qd) * 72 + nt * 8 + gr;
                vb[nt][0] = vp[0];
                vb[nt][1] = vp[4 * 72];
            }
            #pragma unroll
            for (int mt = 0; mt < 2; mt++) {
                const float v0 = __shfl_sync(0xFFFFFFFF, sacc[mt][g][0], srcA);
                const float v1 = __shfl_sync(0xFFFFFFFF, sacc[mt][g][1], srcA);
                const float v2 = __shfl_sync(0xFFFFFFFF, sacc[mt][g][2], srcA);
                const float v3 = __shfl_sync(0xFFFFFFFF, sacc[mt][g][3], srcA);
                const float w0 = __shfl_sync(0xFFFFFFFF, sacc[mt][g][0], srcB);
                const float w1 = __shfl_sync(0xFFFFFFFF, sacc[mt][g][1], srcB);
                const float w2 = __shfl_sync(0xFFFFFFFF, sacc[mt][g][2], srcB);
                const float w3 = __shfl_sync(0xFFFFFFFF, sacc[mt][g][3], srcB);
                uint32_t pa[4];
                pa[0] = f2tf(odd ? v1 : v0);
                pa[1] = f2tf(odd ? v3 : v2);
                pa[2] = f2tf(odd ? w1 : w0);
                pa[3] = f2tf(odd ? w3 : w2);
                #pragma unroll
                for (int nt = 0; nt < 8; nt++)
                    mma8(accO[mt][nt], pa, vb[nt]);
            }
        }
        __syncthreads();
    }

    // ---- normalize + write ctx (combined-head layout)
    #pragma unroll
    for (int mt = 0; mt < 2; mt++) {
        const float i0 = (l_r[mt][0] > 0.f) ? 1.f / l_r[mt][0] : 0.f;
        const float i1 = (l_r[mt][1] > 0.f) ? 1.f / l_r[mt][1] : 0.f;
        const int row0 = q0 + wid * 32 + mt * 16 + gr;
        #pragma unroll
        for (int nt = 0; nt < 8; nt++) {
            const int n = h * HD_ + nt * 8 + qd * 2;
            float2 o0, o1;
            o0.x = accO[mt][nt][0] * i0; o0.y = accO[mt][nt][1] * i0;
            o1.x = accO[mt][nt][2] * i1; o1.y = accO[mt][nt][3] * i1;
            *(float2*)&ctx[((size_t)(b * L_ + row0)) * D_ + n] = o0;
            *(float2*)&ctx[((size_t)(b * L_ + row0 + 8)) * D_ + n] = o1;
        }
    }
}

// ---------------------------------------------------------------------------
extern "C" void kernel_launch(void* const* d_in, const int* in_sizes, int n_in,
                              void* d_out, int out_size)
{
    const float* query = (const float*)d_in[0];
    const float* key_  = (const float*)d_in[1];
    const float* value = (const float*)d_in[2];
    const int*   mask  = (const int*)  d_in[3];
    const float* Wq    = (const float*)d_in[4];
    const float* Wk    = (const float*)d_in[5];
    const float* Wv    = (const float*)d_in[6];
    const float* Wo    = (const float*)d_in[7];
    const float* bo    = (const float*)d_in[8];
    float* out = (float*)d_out;

    float *pq, *pk, *pv, *pc;
    cudaGetSymbolAddress((void**)&pq, g_q);
    cudaGetSymbolAddress((void**)&pk, g_k);
    cudaGetSymbolAddress((void**)&pv, g_v);
    cudaGetSymbolAddress((void**)&pc, g_ctx);

    cudaFuncSetAttribute(gemm_qkv,
                         cudaFuncAttributeMaxDynamicSharedMemorySize, GEMM_SMEM);
    cudaFuncSetAttribute(gemm_out,
                         cudaFuncAttributeMaxDynamicSharedMemorySize, GEMM_SMEM);
    cudaFuncSetAttribute(flash_attn,
                         cudaFuncAttributeMaxDynamicSharedMemorySize, FA_SMEM);

    gemm_qkv<<<dim3(D_ / 128, M_ / 128, 3), 256, GEMM_SMEM>>>(
        query, key_, value, Wq, Wk, Wv, pq, pk, pv);

    flash_attn<<<dim3(B_ * H_, L_ / 128), 128, FA_SMEM>>>(pq, pk, pv, mask, pc);

    gemm_out<<<dim3(D_ / 128, M_ / 128), 256, GEMM_SMEM>>>(pc, Wo, bo, out);
}

// round 10
// speedup vs baseline: 1.1528x; 1.1528x over previous
#include <cuda_runtime.h>
#include <math.h>
#include <stdint.h>

#define B_  2
#define L_  2048
#define D_  1024
#define H_  16
#define HD_ 64
#define M_  (B_*L_)   // 4096

// Scratch (device globals — no allocation allowed). All tf32 bit patterns.
__device__ uint32_t g_xq[M_*D_];
__device__ uint32_t g_xk[M_*D_];
__device__ uint32_t g_xv[M_*D_];
__device__ uint32_t g_wq[D_*D_];
__device__ uint32_t g_wk[D_*D_];
__device__ uint32_t g_wv[D_*D_];
__device__ uint32_t g_wo[D_*D_];
__device__ uint32_t g_q[B_*H_*L_*HD_];
__device__ uint32_t g_k[B_*H_*L_*HD_];
__device__ uint32_t g_v[B_*H_*L_*HD_];
__device__ uint32_t g_ctx[M_*D_];

// ---------------------------------------------------------------------------
// helpers
// ---------------------------------------------------------------------------
__device__ __forceinline__ uint32_t f2tf(float f) {
    uint32_t r;
    asm("cvt.rna.tf32.f32 %0, %1;" : "=r"(r) : "f"(f));
    return r;
}
__device__ __forceinline__ uint32_t smem_u32(const void* p) {
    uint32_t a;
    asm("{ .reg .u64 t; cvta.to.shared.u64 t, %1; cvt.u32.u64 %0, t; }"
        : "=r"(a) : "l"(p));
    return a;
}
__device__ __forceinline__ void cp16(uint32_t s, const void* g) {
    asm volatile("cp.async.cg.shared.global [%0], [%1], 16;" :: "r"(s), "l"(g));
}
// D += A*B, m16n8k8 tf32 (A row-major, B col-major)
__device__ __forceinline__ void mma8(float* d, const uint32_t* a, const uint32_t* b) {
    asm volatile(
        "mma.sync.aligned.m16n8k8.row.col.f32.tf32.tf32.f32 "
        "{%0,%1,%2,%3}, {%4,%5,%6,%7}, {%8,%9}, {%0,%1,%2,%3};"
        : "+f"(d[0]), "+f"(d[1]), "+f"(d[2]), "+f"(d[3])
        : "r"(a[0]), "r"(a[1]), "r"(a[2]), "r"(a[3]), "r"(b[0]), "r"(b[1]));
}
__device__ __forceinline__ void ldm4(uint32_t* r, uint32_t a) {
    asm volatile("ldmatrix.sync.aligned.m8n8.x4.shared.b16 {%0,%1,%2,%3}, [%4];"
                 : "=r"(r[0]), "=r"(r[1]), "=r"(r[2]), "=r"(r[3]) : "r"(a));
}

// ---------------------------------------------------------------------------
// Prologue: fp32 -> tf32 bit pattern (optionally scaled)
// ---------------------------------------------------------------------------
__global__ __launch_bounds__(256) void cvt_tf32(const float4* __restrict__ src,
                                                uint4* __restrict__ dst,
                                                int n4, float scale)
{
    const int i = blockIdx.x * 256 + threadIdx.x;
    if (i < n4) {
        const float4 v = src[i];
        uint4 t;
        t.x = f2tf(v.x * scale); t.y = f2tf(v.y * scale);
        t.z = f2tf(v.z * scale); t.w = f2tf(v.w * scale);
        dst[i] = t;
    }
}

// ===========================================================================
// GEMM body: C[M,N] = X[M,K] @ W[N,K]^T, K=N=1024. Inputs are tf32 bits.
// 128x128 CTA tile, 256 thr (8 warps 2x4), warp tile 64x32, K-chunk 32.
// cp.async double-buffered; ldmatrix fragments; zero cvt in hot loop.
// ===========================================================================
#define GST (128 * 36)           // words per operand per stage
#define GEMM_SMEM (4 * GST * 4)  // 2 stages x (A+B) = 73728 bytes

template<bool SPLIT, bool BIAS>
__device__ __forceinline__ void gemm_body(const uint32_t* __restrict__ X,
                                          const uint32_t* __restrict__ W,
                                          const float* __restrict__ bias,
                                          void* __restrict__ outv,
                                          uint32_t* dsm,
                                          int m0, int n0)
{
    const int tid  = threadIdx.x;
    const int wid  = tid >> 5, lane = tid & 31;
    const int qd   = lane & 3, gr = lane >> 2;
    const int wm   = wid >> 2, wn = wid & 3;

    float acc[4][4][4];
    #pragma unroll
    for (int a = 0; a < 4; a++)
        #pragma unroll
        for (int b = 0; b < 4; b++)
            #pragma unroll
            for (int c = 0; c < 4; c++) acc[a][b][c] = 0.f;

    const int lrow = tid >> 1;            // 0..127
    const int lcol = (tid & 1) * 16;      // 0 / 16
    const uint32_t* Xp = X + (size_t)(m0 + lrow) * D_ + lcol;
    const uint32_t* Wp = W + (size_t)(n0 + lrow) * D_ + lcol;
    const uint32_t sAb0 = smem_u32(dsm + lrow * 36 + lcol);

    const int a_r = ((lane >> 3) & 1) * 8 + (lane & 7);
    const int a_c = (lane >> 4) * 4;
    const int b_r = (lane >> 4) * 8 + (lane & 7);
    const int b_c = ((lane >> 3) & 1) * 4;
    const uint32_t sbase  = smem_u32(dsm);
    const uint32_t aAddr0 = sbase + (((wm * 64 + a_r) * 36 + a_c) << 2);
    const uint32_t bAddr0 = sbase + (GST << 2) + (((wn * 32 + b_r) * 36 + b_c) << 2);

    auto issue = [&](int c, int st) {
        const uint32_t sa = sAb0 + st * (2 * GST * 4);
        const uint32_t sb = sa + GST * 4;
        #pragma unroll
        for (int u = 0; u < 4; u++) {
            cp16(sa + u * 16, Xp + c + u * 4);
            cp16(sb + u * 16, Wp + c + u * 4);
        }
        asm volatile("cp.async.commit_group;");
    };

    issue(0, 0);

    for (int c = 0, st = 0; c < D_; c += 32, st ^= 1) {
        asm volatile("cp.async.wait_group 0;");
        __syncthreads();
        if (c + 32 < D_) issue(c + 32, st ^ 1);   // overlaps compute below

        const uint32_t soff = (uint32_t)st * (2 * GST * 4);
        #pragma unroll
        for (int kk = 0; kk < 32; kk += 8) {
            uint32_t af[4][4], bq[2][4];
            #pragma unroll
            for (int mt = 0; mt < 4; mt++)
                ldm4(af[mt], aAddr0 + soff + ((mt * 16 * 36 + kk) << 2));
            #pragma unroll
            for (int ntp = 0; ntp < 2; ntp++)
                ldm4(bq[ntp], bAddr0 + soff + ((ntp * 16 * 36 + kk) << 2));
            #pragma unroll
            for (int mt = 0; mt < 4; mt++)
                #pragma unroll
                for (int nt = 0; nt < 4; nt++)
                    mma8(acc[mt][nt], af[mt], &bq[nt >> 1][(nt & 1) * 2]);
        }
    }

    #pragma unroll
    for (int mt = 0; mt < 4; mt++) {
        #pragma unroll
        for (int half = 0; half < 2; half++) {
            const int m = m0 + wm * 64 + mt * 16 + gr + half * 8;
            #pragma unroll
            for (int nt = 0; nt < 4; nt++) {
                const int n = n0 + wn * 32 + nt * 8 + qd * 2;
                float2 v;
                v.x = acc[mt][nt][half * 2 + 0];
                v.y = acc[mt][nt][half * 2 + 1];
                if (SPLIT) {
                    // write tf32 bits in [B,H,L,hd] layout
                    const int b = m / L_, l = m % L_, h = n / HD_, d = n % HD_;
                    uint2 t;
                    t.x = f2tf(v.x);
                    t.y = f2tf(v.y);
                    uint32_t* o = (uint32_t*)outv;
                    *(uint2*)&o[(((size_t)(b * H_ + h)) * L_ + l) * HD_ + d] = t;
                } else {
                    if (BIAS) { v.x += bias[n]; v.y += bias[n + 1]; }
                    float* o = (float*)outv;
                    *(float2*)&o[(size_t)m * D_ + n] = v;
                }
            }
        }
    }
}

// Merged Q/K/V projection: blockIdx.z selects the problem.
__global__ __launch_bounds__(256, 2) void gemm_qkv(const uint32_t* __restrict__ xq,
                                                   const uint32_t* __restrict__ xk,
                                                   const uint32_t* __restrict__ xv,
                                                   const uint32_t* __restrict__ wq,
                                                   const uint32_t* __restrict__ wk,
                                                   const uint32_t* __restrict__ wv,
                                                   uint32_t* __restrict__ oq,
                                                   uint32_t* __restrict__ ok,
                                                   uint32_t* __restrict__ ov)
{
    extern __shared__ uint32_t dsm[];
    const uint32_t *X, *W;
    uint32_t* out;
    if (blockIdx.z == 0)      { X = xq; W = wq; out = oq; }
    else if (blockIdx.z == 1) { X = xk; W = wk; out = ok; }
    else                      { X = xv; W = wv; out = ov; }
    gemm_body<true, false>(X, W, nullptr, out, dsm,
                           blockIdx.y * 128, blockIdx.x * 128);
}

__global__ __launch_bounds__(256, 2) void gemm_out(const uint32_t* __restrict__ X,
                                                   const uint32_t* __restrict__ W,
                                                   const float* __restrict__ bias,
                                                   float* __restrict__ out)
{
    extern __shared__ uint32_t dsm[];
    gemm_body<false, true>(X, W, bias, out, dsm,
                           blockIdx.y * 128, blockIdx.x * 128);
}

// ===========================================================================
// Flash attention: q-tile 128, 8 warps x 16 rows (R6 shape), tf32-bit inputs,
// cp.async double-buffered K/V/mask, ldmatrix Q/K fragments, zero load cvt.
// smem: Qs 128x68, 2 stages of {K 64x68, V 64x72, msk 64}.
// NOTE (R9 bug fix): KV stage loader uses 256-thread indexing (tid>>2, 0..63),
// not the 128-thread pattern that overflowed the stage region.
// ===========================================================================
#define FQW (128 * 68)
#define FKW (64 * 68)
#define FVW (64 * 72)
#define FSTG (FKW + FVW + 64)             // 9024 words per stage
#define FA_SMEM ((FQW + 2 * FSTG) * 4)    // 107008 bytes

__global__ __launch_bounds__(256, 2) void flash_attn(const uint32_t* __restrict__ q,
                                                     const uint32_t* __restrict__ k,
                                                     const uint32_t* __restrict__ v,
                                                     const int*      __restrict__ mask,
                                                     uint32_t*       __restrict__ ctx)
{
    extern __shared__ uint32_t smu[];
    uint32_t* Qs = smu;

    const int bh = blockIdx.x;
    const int b  = bh / H_;
    const int h  = bh % H_;
    const int q0 = blockIdx.y * 128;
    const int tid  = threadIdx.x;
    const int wid  = tid >> 5, lane = tid & 31;
    const int qd   = lane & 3, gr = lane >> 2;

    const uint32_t* qbase = q + (size_t)bh * L_ * HD_;
    const uint32_t* kbase = k + (size_t)bh * L_ * HD_;
    const uint32_t* vbase = v + (size_t)bh * L_ * HD_;

    // Q tile: 128 rows, 256 threads -> 2 threads/row, 8 cp16 each
    {
        const int qr = tid >> 1, qc = (tid & 1) * 32;
        const uint32_t* src = qbase + (size_t)(q0 + qr) * HD_ + qc;
        const uint32_t dst = smem_u32(Qs + qr * 68 + qc);
        #pragma unroll
        for (int u = 0; u < 8; u++) cp16(dst + u * 16, src + u * 4);
    }

    // KV stage: 64 rows, 256 threads -> 4 threads/row, 4 cp16 each operand
    const int kvr = tid >> 2, kvc = (tid & 3) * 16;
    auto issueKV = [&](int k0, int s) {
        const uint32_t base = smem_u32(smu) + (FQW + s * FSTG) * 4;
        const uint32_t* ks = kbase + (size_t)(k0 + kvr) * HD_ + kvc;
        const uint32_t* vs = vbase + (size_t)(k0 + kvr) * HD_ + kvc;
        const uint32_t kd = base + ((kvr * 68 + kvc) << 2);
        const uint32_t vd = base + ((FKW + kvr * 72 + kvc) << 2);
        #pragma unroll
        for (int u = 0; u < 4; u++) {
            cp16(kd + u * 16, ks + u * 4);
            cp16(vd + u * 16, vs + u * 4);
        }
        if (tid < 16)
            cp16(base + ((FKW + FVW) << 2) + tid * 16, mask + b * L_ + k0 + tid * 4);
        asm volatile("cp.async.commit_group;");
    };

    issueKV(0, 0);

    float accO[8][4];
    #pragma unroll
    for (int a = 0; a < 8; a++)
        #pragma unroll
        for (int c = 0; c < 4; c++) accO[a][c] = 0.f;
    float m_r0 = -1e30f, m_r1 = -1e30f, l_r0 = 0.f, l_r1 = 0.f;

    // ldmatrix lane addressing
    const int a_r = ((lane >> 3) & 1) * 8 + (lane & 7);
    const int a_c = (lane >> 4) * 4;
    const int k_r = (lane >> 4) * 8 + (lane & 7);
    const int k_c = ((lane >> 3) & 1) * 4;
    const uint32_t qAddr = smem_u32(Qs + (wid * 16 + a_r) * 68 + a_c);

    const int srcA = (lane & ~3) | (qd >> 1);
    const int srcB = srcA + 2;
    const bool odd = (qd & 1);

    for (int k0 = 0, st = 0; k0 < L_; k0 += 64, st ^= 1) {
        asm volatile("cp.async.wait_group 0;");
        __syncthreads();
        if (k0 + 64 < L_) issueKV(k0 + 64, st ^ 1);   // overlaps compute

        const uint32_t sbase = smem_u32(smu) + (FQW + st * FSTG) * 4;
        const uint32_t kAddr = sbase + ((k_r * 68 + k_c) << 2);
        const uint32_t* Vst  = smu + FQW + st * FSTG + FKW;
        const int* mskp = (const int*)(smu + FQW + st * FSTG + FKW + FVW);

        // ---- S = Q*K^T (scale pre-folded into Wq)
        float sacc[8][4];
        #pragma unroll
        for (int a = 0; a < 8; a++)
            #pragma unroll
            for (int c = 0; c < 4; c++) sacc[a][c] = 0.f;

        #pragma unroll
        for (int g = 0; g < 8; g++) {
            uint32_t aq[4], kb[4][4];
            ldm4(aq, qAddr + ((g * 8) << 2));
            #pragma unroll
            for (int ntp = 0; ntp < 4; ntp++)
                ldm4(kb[ntp], kAddr + ((ntp * 16 * 68 + g * 8) << 2));
            #pragma unroll
            for (int nt = 0; nt < 8; nt++)
                mma8(sacc[nt], aq, &kb[nt >> 1][(nt & 1) * 2]);
        }

        // ---- mask + online softmax in registers
        #pragma unroll
        for (int nt = 0; nt < 8; nt++) {
            if (!mskp[8 * nt + 2 * qd])     { sacc[nt][0] = -1e30f; sacc[nt][2] = -1e30f; }
            if (!mskp[8 * nt + 2 * qd + 1]) { sacc[nt][1] = -1e30f; sacc[nt][3] = -1e30f; }
        }
        float rm0 = m_r0, rm1 = m_r1;
        #pragma unroll
        for (int nt = 0; nt < 8; nt++) {
            rm0 = fmaxf(rm0, fmaxf(sacc[nt][0], sacc[nt][1]));
            rm1 = fmaxf(rm1, fmaxf(sacc[nt][2], sacc[nt][3]));
        }
        rm0 = fmaxf(rm0, __shfl_xor_sync(0xFFFFFFFF, rm0, 1));
        rm0 = fmaxf(rm0, __shfl_xor_sync(0xFFFFFFFF, rm0, 2));
        rm1 = fmaxf(rm1, __shfl_xor_sync(0xFFFFFFFF, rm1, 1));
        rm1 = fmaxf(rm1, __shfl_xor_sync(0xFFFFFFFF, rm1, 2));

        const float corr0 = __expf(m_r0 - rm0);
        const float corr1 = __expf(m_r1 - rm1);
        float ls0 = 0.f, ls1 = 0.f;
        #pragma unroll
        for (int nt = 0; nt < 8; nt++) {
            sacc[nt][0] = (sacc[nt][0] < -1e29f) ? 0.f : __expf(sacc[nt][0] - rm0);
            sacc[nt][1] = (sacc[nt][1] < -1e29f) ? 0.f : __expf(sacc[nt][1] - rm0);
            sacc[nt][2] = (sacc[nt][2] < -1e29f) ? 0.f : __expf(sacc[nt][2] - rm1);
            sacc[nt][3] = (sacc[nt][3] < -1e29f) ? 0.f : __expf(sacc[nt][3] - rm1);
            ls0 += sacc[nt][0] + sacc[nt][1];
            ls1 += sacc[nt][2] + sacc[nt][3];
        }
        ls0 += __shfl_xor_sync(0xFFFFFFFF, ls0, 1);
        ls0 += __shfl_xor_sync(0xFFFFFFFF, ls0, 2);
        ls1 += __shfl_xor_sync(0xFFFFFFFF, ls1, 1);
        ls1 += __shfl_xor_sync(0xFFFFFFFF, ls1, 2);

        m_r0 = rm0; m_r1 = rm1;
        l_r0 = l_r0 * corr0 + ls0;
        l_r1 = l_r1 * corr1 + ls1;

        #pragma unroll
        for (int nt = 0; nt < 8; nt++) {
            accO[nt][0] *= corr0; accO[nt][1] *= corr0;
            accO[nt][2] *= corr1; accO[nt][3] *= corr1;
        }

        // ---- P (C-frag) -> A-frag via quad shuffles, then O += P @ V
        #pragma unroll
        for (int g = 0; g < 8; g++) {
            const float v0 = __shfl_sync(0xFFFFFFFF, sacc[g][0], srcA);
            const float v1 = __shfl_sync(0xFFFFFFFF, sacc[g][1], srcA);
            const float v2 = __shfl_sync(0xFFFFFFFF, sacc[g][2], srcA);
            const float v3 = __shfl_sync(0xFFFFFFFF, sacc[g][3], srcA);
            const float w0 = __shfl_sync(0xFFFFFFFF, sacc[g][0], srcB);
            const float w1 = __shfl_sync(0xFFFFFFFF, sacc[g][1], srcB);
            const float w2 = __shfl_sync(0xFFFFFFFF, sacc[g][2], srcB);
            const float w3 = __shfl_sync(0xFFFFFFFF, sacc[g][3], srcB);
            uint32_t pa[4];
            pa[0] = f2tf(odd ? v1 : v0);
            pa[1] = f2tf(odd ? v3 : v2);
            pa[2] = f2tf(odd ? w1 : w0);
            pa[3] = f2tf(odd ? w3 : w2);
            #pragma unroll
            for (int nt = 0; nt < 8; nt++) {
                uint32_t bf[2];
                const uint32_t* vp = Vst + (g * 8 + qd) * 72 + nt * 8 + gr;
                bf[0] = vp[0];
                bf[1] = vp[4 * 72];
                mma8(accO[nt], pa, bf);
            }
        }
    }

    // ---- normalize + write ctx as tf32 bits (combined-head layout)
    {
        const float i0 = (l_r0 > 0.f) ? 1.f / l_r0 : 0.f;
        const float i1 = (l_r1 > 0.f) ? 1.f / l_r1 : 0.f;
        const int row0 = q0 + wid * 16 + gr;
        #pragma unroll
        for (int nt = 0; nt < 8; nt++) {
            const int n = h * HD_ + nt * 8 + qd * 2;
            uint2 o0, o1;
            o0.x = f2tf(accO[nt][0] * i0); o0.y = f2tf(accO[nt][1] * i0);
            o1.x = f2tf(accO[nt][2] * i1); o1.y = f2tf(accO[nt][3] * i1);
            *(uint2*)&ctx[((size_t)(b * L_ + row0)) * D_ + n] = o0;
            *(uint2*)&ctx[((size_t)(b * L_ + row0 + 8)) * D_ + n] = o1;
        }
    }
}

// ---------------------------------------------------------------------------
extern "C" void kernel_launch(void* const* d_in, const int* in_sizes, int n_in,
                              void* d_out, int out_size)
{
    const float* query = (const float*)d_in[0];
    const float* key_  = (const float*)d_in[1];
    const float* value = (const float*)d_in[2];
    const int*   mask  = (const int*)  d_in[3];
    const float* Wq    = (const float*)d_in[4];
    const float* Wk    = (const float*)d_in[5];
    const float* Wv    = (const float*)d_in[6];
    const float* Wo    = (const float*)d_in[7];
    const float* bo    = (const float*)d_in[8];
    float* out = (float*)d_out;

    uint32_t *xq, *xk, *xv, *wq, *wk, *wv, *wo, *pq, *pk, *pv, *pc;
    cudaGetSymbolAddress((void**)&xq, g_xq);
    cudaGetSymbolAddress((void**)&xk, g_xk);
    cudaGetSymbolAddress((void**)&xv, g_xv);
    cudaGetSymbolAddress((void**)&wq, g_wq);
    cudaGetSymbolAddress((void**)&wk, g_wk);
    cudaGetSymbolAddress((void**)&wv, g_wv);
    cudaGetSymbolAddress((void**)&wo, g_wo);
    cudaGetSymbolAddress((void**)&pq, g_q);
    cudaGetSymbolAddress((void**)&pk, g_k);
    cudaGetSymbolAddress((void**)&pv, g_v);
    cudaGetSymbolAddress((void**)&pc, g_ctx);

    cudaFuncSetAttribute(gemm_qkv,
                         cudaFuncAttributeMaxDynamicSharedMemorySize, GEMM_SMEM);
    cudaFuncSetAttribute(gemm_out,
                         cudaFuncAttributeMaxDynamicSharedMemorySize, GEMM_SMEM);
    cudaFuncSetAttribute(flash_attn,
                         cudaFuncAttributeMaxDynamicSharedMemorySize, FA_SMEM);

    const int nx4 = M_ * D_ / 4;   // 1,048,576
    const int nw4 = D_ * D_ / 4;   //   262,144
    cvt_tf32<<<nx4 / 256, 256>>>((const float4*)query, (uint4*)xq, nx4, 1.0f);
    cvt_tf32<<<nx4 / 256, 256>>>((const float4*)key_,  (uint4*)xk, nx4, 1.0f);
    cvt_tf32<<<nx4 / 256, 256>>>((const float4*)value, (uint4*)xv, nx4, 1.0f);
    cvt_tf32<<<nw4 / 256, 256>>>((const float4*)Wq, (uint4*)wq, nw4, 0.125f);
    cvt_tf32<<<nw4 / 256, 256>>>((const float4*)Wk, (uint4*)wk, nw4, 1.0f);
    cvt_tf32<<<nw4 / 256, 256>>>((const float4*)Wv, (uint4*)wv, nw4, 1.0f);
    cvt_tf32<<<nw4 / 256, 256>>>((const float4*)Wo, (uint4*)wo, nw4, 1.0f);

    gemm_qkv<<<dim3(D_ / 128, M_ / 128, 3), 256, GEMM_SMEM>>>(
        xq, xk, xv, wq, wk, wv, pq, pk, pv);

    flash_attn<<<dim3(B_ * H_, L_ / 128), 256, FA_SMEM>>>(pq, pk, pv, mask, pc);

    gemm_out<<<dim3(D_ / 128, M_ / 128), 256, GEMM_SMEM>>>(pc, wo, bo, out);
}

// round 12
// speedup vs baseline: 1.1923x; 1.0342x over previous
#include <cuda_runtime.h>
#include <math.h>
#include <stdint.h>

#define B_  2
#define L_  2048
#define D_  1024
#define H_  16
#define HD_ 64
#define M_  (B_*L_)   // 4096

// Scratch (device globals — no allocation allowed). All tf32 bit patterns.
__device__ uint32_t g_xq[M_*D_];
__device__ uint32_t g_xk[M_*D_];
__device__ uint32_t g_xv[M_*D_];
__device__ uint32_t g_wq[D_*D_];
__device__ uint32_t g_wk[D_*D_];
__device__ uint32_t g_wv[D_*D_];
__device__ uint32_t g_wo[D_*D_];
__device__ uint32_t g_q[B_*H_*L_*HD_];
__device__ uint32_t g_k[B_*H_*L_*HD_];
__device__ uint32_t g_v[B_*H_*L_*HD_];   // TRANSPOSED: [bh][dim][key]
__device__ uint32_t g_ctx[M_*D_];

// ---------------------------------------------------------------------------
// helpers
// ---------------------------------------------------------------------------
__device__ __forceinline__ uint32_t f2tf(float f) {
    uint32_t r;
    asm("cvt.rna.tf32.f32 %0, %1;" : "=r"(r) : "f"(f));
    return r;
}
__device__ __forceinline__ uint32_t smem_u32(const void* p) {
    uint32_t a;
    asm("{ .reg .u64 t; cvta.to.shared.u64 t, %1; cvt.u32.u64 %0, t; }"
        : "=r"(a) : "l"(p));
    return a;
}
__device__ __forceinline__ void cp16(uint32_t s, const void* g) {
    asm volatile("cp.async.cg.shared.global [%0], [%1], 16;" :: "r"(s), "l"(g));
}
// D += A*B, m16n8k8 tf32 (A row-major, B col-major)
__device__ __forceinline__ void mma8(float* d, const uint32_t* a, const uint32_t* b) {
    asm volatile(
        "mma.sync.aligned.m16n8k8.row.col.f32.tf32.tf32.f32 "
        "{%0,%1,%2,%3}, {%4,%5,%6,%7}, {%8,%9}, {%0,%1,%2,%3};"
        : "+f"(d[0]), "+f"(d[1]), "+f"(d[2]), "+f"(d[3])
        : "r"(a[0]), "r"(a[1]), "r"(a[2]), "r"(a[3]), "r"(b[0]), "r"(b[1]));
}
__device__ __forceinline__ void ldm4(uint32_t* r, uint32_t a) {
    asm volatile("ldmatrix.sync.aligned.m8n8.x4.shared.b16 {%0,%1,%2,%3}, [%4];"
                 : "=r"(r[0]), "=r"(r[1]), "=r"(r[2]), "=r"(r[3]) : "r"(a));
}

// ---------------------------------------------------------------------------
// Prologue: fp32 -> tf32 for ALL 7 tensors in one launch.
// Region layout (uint4 units): xq,xk,xv: NX4 each; wq(scaled),wk,wv,wo: NW4.
// ---------------------------------------------------------------------------
#define NX4 (M_*D_/4)   // 1,048,576
#define NW4 (D_*D_/4)   //   262,144
#define NCVT (3*NX4 + 4*NW4)

__global__ __launch_bounds__(256) void cvt_all(const float4* __restrict__ q,
                                               const float4* __restrict__ k,
                                               const float4* __restrict__ v,
                                               const float4* __restrict__ Wq,
                                               const float4* __restrict__ Wk,
                                               const float4* __restrict__ Wv,
                                               const float4* __restrict__ Wo,
                                               uint4* __restrict__ xq,
                                               uint4* __restrict__ xk,
                                               uint4* __restrict__ xv,
                                               uint4* __restrict__ wq,
                                               uint4* __restrict__ wk,
                                               uint4* __restrict__ wv,
                                               uint4* __restrict__ wo)
{
    int i = blockIdx.x * 256 + threadIdx.x;
    const float4* src;
    uint4* dst;
    float scale = 1.0f;
    if (i < 3 * NX4) {
        if (i < NX4)          { src = q; dst = xq; }
        else if (i < 2 * NX4) { src = k; dst = xk; i -= NX4; }
        else                  { src = v; dst = xv; i -= 2 * NX4; }
    } else {
        i -= 3 * NX4;
        if (i < NW4)          { src = Wq; dst = wq; scale = 0.125f; }
        else if (i < 2 * NW4) { src = Wk; dst = wk; i -= NW4; }
        else if (i < 3 * NW4) { src = Wv; dst = wv; i -= 2 * NW4; }
        else                  { src = Wo; dst = wo; i -= 3 * NW4; }
    }
    const float4 x = src[i];
    uint4 t;
    t.x = f2tf(x.x * scale); t.y = f2tf(x.y * scale);
    t.z = f2tf(x.z * scale); t.w = f2tf(x.w * scale);
    dst[i] = t;
}

// ===========================================================================
// GEMM body: C[M,N] = X[M,K] @ W[N,K]^T, K=N=1024. Inputs are tf32 bits.
// MODE 0: fp32 out + bias (row-major). MODE 1: tf32 [B,H,L,hd] (Q,K).
// MODE 2: tf32 TRANSPOSED [B,H,hd,L] (V, for ldmatrix B-frags in flash).
// 128x128 CTA tile, 256 thr (8 warps 2x4), warp tile 64x32, K-chunk 32.
// ===========================================================================
#define GST (128 * 36)           // words per operand per stage
#define GEMM_SMEM (4 * GST * 4)  // 2 stages x (A+B) = 73728 bytes

template<int MODE>
__device__ __forceinline__ void gemm_body(const uint32_t* __restrict__ X,
                                          const uint32_t* __restrict__ W,
                                          const float* __restrict__ bias,
                                          void* __restrict__ outv,
                                          uint32_t* dsm,
                                          int m0, int n0)
{
    const int tid  = threadIdx.x;
    const int wid  = tid >> 5, lane = tid & 31;
    const int qd   = lane & 3, gr = lane >> 2;
    const int wm   = wid >> 2, wn = wid & 3;

    float acc[4][4][4];
    #pragma unroll
    for (int a = 0; a < 4; a++)
        #pragma unroll
        for (int b = 0; b < 4; b++)
            #pragma unroll
            for (int c = 0; c < 4; c++) acc[a][b][c] = 0.f;

    const int lrow = tid >> 1;            // 0..127
    const int lcol = (tid & 1) * 16;      // 0 / 16
    const uint32_t* Xp = X + (size_t)(m0 + lrow) * D_ + lcol;
    const uint32_t* Wp = W + (size_t)(n0 + lrow) * D_ + lcol;
    const uint32_t sAb0 = smem_u32(dsm + lrow * 36 + lcol);

    const int a_r = ((lane >> 3) & 1) * 8 + (lane & 7);
    const int a_c = (lane >> 4) * 4;
    const int b_r = (lane >> 4) * 8 + (lane & 7);
    const int b_c = ((lane >> 3) & 1) * 4;
    const uint32_t sbase  = smem_u32(dsm);
    const uint32_t aAddr0 = sbase + (((wm * 64 + a_r) * 36 + a_c) << 2);
    const uint32_t bAddr0 = sbase + (GST << 2) + (((wn * 32 + b_r) * 36 + b_c) << 2);

    auto issue = [&](int c, int st) {
        const uint32_t sa = sAb0 + st * (2 * GST * 4);
        const uint32_t sb = sa + GST * 4;
        #pragma unroll
        for (int u = 0; u < 4; u++) {
            cp16(sa + u * 16, Xp + c + u * 4);
            cp16(sb + u * 16, Wp + c + u * 4);
        }
        asm volatile("cp.async.commit_group;");
    };

    issue(0, 0);

    for (int c = 0, st = 0; c < D_; c += 32, st ^= 1) {
        asm volatile("cp.async.wait_group 0;");
        __syncthreads();
        if (c + 32 < D_) issue(c + 32, st ^ 1);   // overlaps compute below

        const uint32_t soff = (uint32_t)st * (2 * GST * 4);
        #pragma unroll
        for (int kk = 0; kk < 32; kk += 8) {
            uint32_t af[4][4], bq[2][4];
            #pragma unroll
            for (int mt = 0; mt < 4; mt++)
                ldm4(af[mt], aAddr0 + soff + ((mt * 16 * 36 + kk) << 2));
            #pragma unroll
            for (int ntp = 0; ntp < 2; ntp++)
                ldm4(bq[ntp], bAddr0 + soff + ((ntp * 16 * 36 + kk) << 2));
            #pragma unroll
            for (int mt = 0; mt < 4; mt++)
                #pragma unroll
                for (int nt = 0; nt < 4; nt++)
                    mma8(acc[mt][nt], af[mt], &bq[nt >> 1][(nt & 1) * 2]);
        }
    }

    #pragma unroll
    for (int mt = 0; mt < 4; mt++) {
        #pragma unroll
        for (int half = 0; half < 2; half++) {
            const int m = m0 + wm * 64 + mt * 16 + gr + half * 8;
            #pragma unroll
            for (int nt = 0; nt < 4; nt++) {
                const int n = n0 + wn * 32 + nt * 8 + qd * 2;
                float2 v;
                v.x = acc[mt][nt][half * 2 + 0];
                v.y = acc[mt][nt][half * 2 + 1];
                if (MODE == 1) {
                    const int b = m / L_, l = m % L_, h = n / HD_, d = n % HD_;
                    uint2 t;
                    t.x = f2tf(v.x);
                    t.y = f2tf(v.y);
                    uint32_t* o = (uint32_t*)outv;
                    *(uint2*)&o[(((size_t)(b * H_ + h)) * L_ + l) * HD_ + d] = t;
                } else if (MODE == 2) {
                    // transposed: [bh][dim][key]; two scalar stores, 32B-coalesced over gr
                    const int b = m / L_, l = m % L_, h = n / HD_, d = n % HD_;
                    uint32_t* o = (uint32_t*)outv;
                    const size_t base = (((size_t)(b * H_ + h)) * HD_ + d) * L_ + l;
                    o[base]      = f2tf(v.x);
                    o[base + L_] = f2tf(v.y);
                } else {
                    v.x += bias[n]; v.y += bias[n + 1];
                    float* o = (float*)outv;
                    *(float2*)&o[(size_t)m * D_ + n] = v;
                }
            }
        }
    }
}

// Merged Q/K/V projection: blockIdx.z selects the problem.
__global__ __launch_bounds__(256, 2) void gemm_qkv(const uint32_t* __restrict__ xq,
                                                   const uint32_t* __restrict__ xk,
                                                   const uint32_t* __restrict__ xv,
                                                   const uint32_t* __restrict__ wq,
                                                   const uint32_t* __restrict__ wk,
                                                   const uint32_t* __restrict__ wv,
                                                   uint32_t* __restrict__ oq,
                                                   uint32_t* __restrict__ ok,
                                                   uint32_t* __restrict__ ov)
{
    extern __shared__ uint32_t dsm[];
    if (blockIdx.z == 0)
        gemm_body<1>(xq, wq, nullptr, oq, dsm, blockIdx.y * 128, blockIdx.x * 128);
    else if (blockIdx.z == 1)
        gemm_body<1>(xk, wk, nullptr, ok, dsm, blockIdx.y * 128, blockIdx.x * 128);
    else
        gemm_body<2>(xv, wv, nullptr, ov, dsm, blockIdx.y * 128, blockIdx.x * 128);
}

__global__ __launch_bounds__(256, 2) void gemm_out(const uint32_t* __restrict__ X,
                                                   const uint32_t* __restrict__ W,
                                                   const float* __restrict__ bias,
                                                   float* __restrict__ out)
{
    extern __shared__ uint32_t dsm[];
    gemm_body<0>(X, W, bias, out, dsm, blockIdx.y * 128, blockIdx.x * 128);
}

// ===========================================================================
// Flash attention: q-tile 128, 8 warps x 16 rows, tf32-bit inputs.
// V is pre-transposed [bh][dim][key] -> B-fragments via ldmatrix (same
// verified path as K). cp.async double-buffered K/Vt/mask stages.
// smem: Qs 128x68, 2 stages of {K 64x68, Vt 64x68, msk 64}.
// ===========================================================================
#define FQW (128 * 68)
#define FKW (64 * 68)
#define FVW (64 * 68)
#define FSTG (FKW + FVW + 64)             // 8768 words per stage
#define FA_SMEM ((FQW + 2 * FSTG) * 4)    // 104960 bytes

__global__ __launch_bounds__(256, 2) void flash_attn(const uint32_t* __restrict__ q,
                                                     const uint32_t* __restrict__ k,
                                                     const uint32_t* __restrict__ vt,
                                                     const int*      __restrict__ mask,
                                                     uint32_t*       __restrict__ ctx)
{
    extern __shared__ uint32_t smu[];
    uint32_t* Qs = smu;

    const int bh = blockIdx.x;
    const int b  = bh / H_;
    const int h  = bh % H_;
    const int q0 = blockIdx.y * 128;
    const int tid  = threadIdx.x;
    const int wid  = tid >> 5, lane = tid & 31;
    const int qd   = lane & 3, gr = lane >> 2;

    const uint32_t* qbase  = q  + (size_t)bh * L_ * HD_;
    const uint32_t* kbase  = k  + (size_t)bh * L_ * HD_;
    const uint32_t* vtbase = vt + (size_t)bh * HD_ * L_;

    // Q tile: 128 rows, 256 threads -> 2 threads/row, 8 cp16 each
    {
        const int qr = tid >> 1, qc = (tid & 1) * 32;
        const uint32_t* src = qbase + (size_t)(q0 + qr) * HD_ + qc;
        const uint32_t dst = smem_u32(Qs + qr * 68 + qc);
        #pragma unroll
        for (int u = 0; u < 8; u++) cp16(dst + u * 16, src + u * 4);
    }

    // KV stage: 64 rows each, 256 threads -> 4 threads/row, 4 cp16 each.
    // K row = key (64 dims per row); Vt row = dim (64 keys per row).
    const int kvr = tid >> 2, kvc = (tid & 3) * 16;
    auto issueKV = [&](int k0, int s) {
        const uint32_t base = smem_u32(smu) + (FQW + s * FSTG) * 4;
        const uint32_t* ks = kbase  + (size_t)(k0 + kvr) * HD_ + kvc;
        const uint32_t* vs = vtbase + (size_t)kvr * L_ + k0 + kvc;
        const uint32_t kd = base + ((kvr * 68 + kvc) << 2);
        const uint32_t vd = base + ((FKW + kvr * 68 + kvc) << 2);
        #pragma unroll
        for (int u = 0; u < 4; u++) {
            cp16(kd + u * 16, ks + u * 4);
            cp16(vd + u * 16, vs + u * 4);
        }
        if (tid < 16)
            cp16(base + ((FKW + FVW) << 2) + tid * 16, mask + b * L_ + k0 + tid * 4);
        asm volatile("cp.async.commit_group;");
    };

    issueKV(0, 0);

    float accO[8][4];
    #pragma unroll
    for (int a = 0; a < 8; a++)
        #pragma unroll
        for (int c = 0; c < 4; c++) accO[a][c] = 0.f;
    float m_r0 = -1e30f, m_r1 = -1e30f, l_r0 = 0.f, l_r1 = 0.f;

    // ldmatrix lane addressing
    const int a_r = ((lane >> 3) & 1) * 8 + (lane & 7);
    const int a_c = (lane >> 4) * 4;
    const int k_r = (lane >> 4) * 8 + (lane & 7);
    const int k_c = ((lane >> 3) & 1) * 4;
    const uint32_t qAddr = smem_u32(Qs + (wid * 16 + a_r) * 68 + a_c);

    const int srcA = (lane & ~3) | (qd >> 1);
    const int srcB = srcA + 2;
    const bool odd = (qd & 1);

    for (int k0 = 0, st = 0; k0 < L_; k0 += 64, st ^= 1) {
        asm volatile("cp.async.wait_group 0;");
        __syncthreads();
        if (k0 + 64 < L_) issueKV(k0 + 64, st ^ 1);   // overlaps compute

        const uint32_t sbase = smem_u32(smu) + (FQW + st * FSTG) * 4;
        const uint32_t kAddr = sbase + ((k_r * 68 + k_c) << 2);
        const uint32_t vAddr = sbase + (FKW << 2) + ((k_r * 68 + k_c) << 2);
        const int* mskp = (const int*)(smu + FQW + st * FSTG + FKW + FVW);

        // ---- S = Q*K^T (scale pre-folded into Wq)
        float sacc[8][4];
        #pragma unroll
        for (int a = 0; a < 8; a++)
            #pragma unroll
            for (int c = 0; c < 4; c++) sacc[a][c] = 0.f;

        #pragma unroll
        for (int g = 0; g < 8; g++) {
            uint32_t aq[4], kb[4][4];
            ldm4(aq, qAddr + ((g * 8) << 2));
            #pragma unroll
            for (int ntp = 0; ntp < 4; ntp++)
                ldm4(kb[ntp], kAddr + ((ntp * 16 * 68 + g * 8) << 2));
            #pragma unroll
            for (int nt = 0; nt < 8; nt++)
                mma8(sacc[nt], aq, &kb[nt >> 1][(nt & 1) * 2]);
        }

        // ---- mask + online softmax in registers
        #pragma unroll
        for (int nt = 0; nt < 8; nt++) {
            if (!mskp[8 * nt + 2 * qd])     { sacc[nt][0] = -1e30f; sacc[nt][2] = -1e30f; }
            if (!mskp[8 * nt + 2 * qd + 1]) { sacc[nt][1] = -1e30f; sacc[nt][3] = -1e30f; }
        }
        float rm0 = m_r0, rm1 = m_r1;
        #pragma unroll
        for (int nt = 0; nt < 8; nt++) {
            rm0 = fmaxf(rm0, fmaxf(sacc[nt][0], sacc[nt][1]));
            rm1 = fmaxf(rm1, fmaxf(sacc[nt][2], sacc[nt][3]));
        }
        rm0 = fmaxf(rm0, __shfl_xor_sync(0xFFFFFFFF, rm0, 1));
        rm0 = fmaxf(rm0, __shfl_xor_sync(0xFFFFFFFF, rm0, 2));
        rm1 = fmaxf(rm1, __shfl_xor_sync(0xFFFFFFFF, rm1, 1));
        rm1 = fmaxf(rm1, __shfl_xor_sync(0xFFFFFFFF, rm1, 2));

        const float corr0 = __expf(m_r0 - rm0);
        const float corr1 = __expf(m_r1 - rm1);
        float ls0 = 0.f, ls1 = 0.f;
        #pragma unroll
        for (int nt = 0; nt < 8; nt++) {
            sacc[nt][0] = (sacc[nt][0] < -1e29f) ? 0.f : __expf(sacc[nt][0] - rm0);
            sacc[nt][1] = (sacc[nt][1] < -1e29f) ? 0.f : __expf(sacc[nt][1] - rm0);
            sacc[nt][2] = (sacc[nt][2] < -1e29f) ? 0.f : __expf(sacc[nt][2] - rm1);
            sacc[nt][3] = (sacc[nt][3] < -1e29f) ? 0.f : __expf(sacc[nt][3] - rm1);
            ls0 += sacc[nt][0] + sacc[nt][1];
            ls1 += sacc[nt][2] + sacc[nt][3];
        }
        ls0 += __shfl_xor_sync(0xFFFFFFFF, ls0, 1);
        ls0 += __shfl_xor_sync(0xFFFFFFFF, ls0, 2);
        ls1 += __shfl_xor_sync(0xFFFFFFFF, ls1, 1);
        ls1 += __shfl_xor_sync(0xFFFFFFFF, ls1, 2);

        m_r0 = rm0; m_r1 = rm1;
        l_r0 = l_r0 * corr0 + ls0;
        l_r1 = l_r1 * corr1 + ls1;

        #pragma unroll
        for (int nt = 0; nt < 8; nt++) {
            accO[nt][0] *= corr0; accO[nt][1] *= corr0;
            accO[nt][2] *= corr1; accO[nt][3] *= corr1;
        }

        // ---- P (C-frag) -> A-frag via quad shuffles, then O += P @ Vt
        #pragma unroll
        for (int g = 0; g < 8; g++) {
            const float v0 = __shfl_sync(0xFFFFFFFF, sacc[g][0], srcA);
            const float v1 = __shfl_sync(0xFFFFFFFF, sacc[g][1], srcA);
            const float v2 = __shfl_sync(0xFFFFFFFF, sacc[g][2], srcA);
            const float v3 = __shfl_sync(0xFFFFFFFF, sacc[g][3], srcA);
            const float w0 = __shfl_sync(0xFFFFFFFF, sacc[g][0], srcB);
            const float w1 = __shfl_sync(0xFFFFFFFF, sacc[g][1], srcB);
            const float w2 = __shfl_sync(0xFFFFFFFF, sacc[g][2], srcB);
            const float w3 = __shfl_sync(0xFFFFFFFF, sacc[g][3], srcB);
            uint32_t pa[4];
            pa[0] = f2tf(odd ? v1 : v0);
            pa[1] = f2tf(odd ? v3 : v2);
            pa[2] = f2tf(odd ? w1 : w0);
            pa[3] = f2tf(odd ? w3 : w2);
            uint32_t vb[4][4];
            #pragma unroll
            for (int ntp = 0; ntp < 4; ntp++)
                ldm4(vb[ntp], vAddr + ((ntp * 16 * 68 + g * 8) << 2));
            #pragma unroll
            for (int nt = 0; nt < 8; nt++)
                mma8(accO[nt], pa, &vb[nt >> 1][(nt & 1) * 2]);
        }
    }

    // ---- normalize + write ctx as tf32 bits (combined-head layout)
    {
        const float i0 = (l_r0 > 0.f) ? 1.f / l_r0 : 0.f;
        const float i1 = (l_r1 > 0.f) ? 1.f / l_r1 : 0.f;
        const int row0 = q0 + wid * 16 + gr;
        #pragma unroll
        for (int nt = 0; nt < 8; nt++) {
            const int n = h * HD_ + nt * 8 + qd * 2;
            uint2 o0, o1;
            o0.x = f2tf(accO[nt][0] * i0); o0.y = f2tf(accO[nt][1] * i0);
            o1.x = f2tf(accO[nt][2] * i1); o1.y = f2tf(accO[nt][3] * i1);
            *(uint2*)&ctx[((size_t)(b * L_ + row0)) * D_ + n] = o0;
            *(uint2*)&ctx[((size_t)(b * L_ + row0 + 8)) * D_ + n] = o1;
        }
    }
}

// ---------------------------------------------------------------------------
extern "C" void kernel_launch(void* const* d_in, const int* in_sizes, int n_in,
                              void* d_out, int out_size)
{
    const float* query = (const float*)d_in[0];
    const float* key_  = (const float*)d_in[1];
    const float* value = (const float*)d_in[2];
    const int*   mask  = (const int*)  d_in[3];
    const float* Wq    = (const float*)d_in[4];
    const float* Wk    = (const float*)d_in[5];
    const float* Wv    = (const float*)d_in[6];
    const float* Wo    = (const float*)d_in[7];
    const float* bo    = (const float*)d_in[8];
    float* out = (float*)d_out;

    uint32_t *xq, *xk, *xv, *wq, *wk, *wv, *wo, *pq, *pk, *pv, *pc;
    cudaGetSymbolAddress((void**)&xq, g_xq);
    cudaGetSymbolAddress((void**)&xk, g_xk);
    cudaGetSymbolAddress((void**)&xv, g_xv);
    cudaGetSymbolAddress((void**)&wq, g_wq);
    cudaGetSymbolAddress((void**)&wk, g_wk);
    cudaGetSymbolAddress((void**)&wv, g_wv);
    cudaGetSymbolAddress((void**)&wo, g_wo);
    cudaGetSymbolAddress((void**)&pq, g_q);
    cudaGetSymbolAddress((void**)&pk, g_k);
    cudaGetSymbolAddress((void**)&pv, g_v);
    cudaGetSymbolAddress((void**)&pc, g_ctx);

    cudaFuncSetAttribute(gemm_qkv,
                         cudaFuncAttributeMaxDynamicSharedMemorySize, GEMM_SMEM);
    cudaFuncSetAttribute(gemm_out,
                         cudaFuncAttributeMaxDynamicSharedMemorySize, GEMM_SMEM);
    cudaFuncSetAttribute(flash_attn,
                         cudaFuncAttributeMaxDynamicSharedMemorySize, FA_SMEM);

    cvt_all<<<NCVT / 256, 256>>>((const float4*)query, (const float4*)key_,
                                 (const float4*)value, (const float4*)Wq,
                                 (const float4*)Wk, (const float4*)Wv,
                                 (const float4*)Wo,
                                 (uint4*)xq, (uint4*)xk, (uint4*)xv,
                                 (uint4*)wq, (uint4*)wk, (uint4*)wv, (uint4*)wo);

    gemm_qkv<<<dim3(D_ / 128, M_ / 128, 3), 256, GEMM_SMEM>>>(
        xq, xk, xv, wq, wk, wv, pq, pk, pv);

    flash_attn<<<dim3(B_ * H_, L_ / 128), 256, FA_SMEM>>>(pq, pk, pv, mask, pc);

    gemm_out<<<dim3(D_ / 128, M_ / 128), 256, GEMM_SMEM>>>(pc, wo, bo, out);
}

// round 16
// speedup vs baseline: 1.1967x; 1.0037x over previous
#include <cuda_runtime.h>
#include <math.h>
#include <stdint.h>

#define B_  2
#define L_  2048
#define D_  1024
#define H_  16
#define HD_ 64
#define M_  (B_*L_)   // 4096

// Scratch (device globals — no allocation allowed). All tf32 bit patterns.
__device__ uint32_t g_xq[M_*D_];
__device__ uint32_t g_xk[M_*D_];
__device__ uint32_t g_xv[M_*D_];
__device__ uint32_t g_wq[D_*D_];
__device__ uint32_t g_wk[D_*D_];
__device__ uint32_t g_wv[D_*D_];
__device__ uint32_t g_wo[D_*D_];
__device__ uint32_t g_q[B_*H_*L_*HD_];
__device__ uint32_t g_k[B_*H_*L_*HD_];
__device__ uint32_t g_v[B_*H_*L_*HD_];   // TRANSPOSED: [bh][dim][key]
__device__ uint32_t g_ctx[M_*D_];

// ---------------------------------------------------------------------------
// helpers
// ---------------------------------------------------------------------------
__device__ __forceinline__ uint32_t f2tf(float f) {
    uint32_t r;
    asm("cvt.rna.tf32.f32 %0, %1;" : "=r"(r) : "f"(f));
    return r;
}
__device__ __forceinline__ float ex2(float x) {
    float y;
    asm("ex2.approx.f32 %0, %1;" : "=f"(y) : "f"(x));
    return y;
}
__device__ __forceinline__ uint32_t smem_u32(const void* p) {
    uint32_t a;
    asm("{ .reg .u64 t; cvta.to.shared.u64 t, %1; cvt.u32.u64 %0, t; }"
        : "=r"(a) : "l"(p));
    return a;
}
__device__ __forceinline__ void cp16(uint32_t s, const void* g) {
    asm volatile("cp.async.cg.shared.global [%0], [%1], 16;" :: "r"(s), "l"(g));
}
// D += A*B, m16n8k8 tf32 (A row-major, B col-major)
__device__ __forceinline__ void mma8(float* d, const uint32_t* a, const uint32_t* b) {
    asm volatile(
        "mma.sync.aligned.m16n8k8.row.col.f32.tf32.tf32.f32 "
        "{%0,%1,%2,%3}, {%4,%5,%6,%7}, {%8,%9}, {%0,%1,%2,%3};"
        : "+f"(d[0]), "+f"(d[1]), "+f"(d[2]), "+f"(d[3])
        : "r"(a[0]), "r"(a[1]), "r"(a[2]), "r"(a[3]), "r"(b[0]), "r"(b[1]));
}
__device__ __forceinline__ void ldm4(uint32_t* r, uint32_t a) {
    asm volatile("ldmatrix.sync.aligned.m8n8.x4.shared.b16 {%0,%1,%2,%3}, [%4];"
                 : "=r"(r[0]), "=r"(r[1]), "=r"(r[2]), "=r"(r[3]) : "r"(a));
}

// ---------------------------------------------------------------------------
// Prologue: fp32 -> tf32 for ALL 7 tensors in one launch.
// Wq is pre-scaled by (1/8)*log2(e): softmax then runs in exp2 domain.
// ---------------------------------------------------------------------------
#define NX4 (M_*D_/4)   // 1,048,576
#define NW4 (D_*D_/4)   //   262,144
#define NCVT (3*NX4 + 4*NW4)
#define QSCALE (0.125f * 1.4426950408889634f)

__global__ __launch_bounds__(256) void cvt_all(const float4* __restrict__ q,
                                               const float4* __restrict__ k,
                                               const float4* __restrict__ v,
                                               const float4* __restrict__ Wq,
                                               const float4* __restrict__ Wk,
                                               const float4* __restrict__ Wv,
                                               const float4* __restrict__ Wo,
                                               uint4* __restrict__ xq,
                                               uint4* __restrict__ xk,
                                               uint4* __restrict__ xv,
                                               uint4* __restrict__ wq,
                                               uint4* __restrict__ wk,
                                               uint4* __restrict__ wv,
                                               uint4* __restrict__ wo)
{
    int i = blockIdx.x * 256 + threadIdx.x;
    const float4* src;
    uint4* dst;
    float scale = 1.0f;
    if (i < 3 * NX4) {
        if (i < NX4)          { src = q; dst = xq; }
        else if (i < 2 * NX4) { src = k; dst = xk; i -= NX4; }
        else                  { src = v; dst = xv; i -= 2 * NX4; }
    } else {
        i -= 3 * NX4;
        if (i < NW4)          { src = Wq; dst = wq; scale = QSCALE; }
        else if (i < 2 * NW4) { src = Wk; dst = wk; i -= NW4; }
        else if (i < 3 * NW4) { src = Wv; dst = wv; i -= 2 * NW4; }
        else                  { src = Wo; dst = wo; i -= 3 * NW4; }
    }
    const float4 x = src[i];
    uint4 t;
    t.x = f2tf(x.x * scale); t.y = f2tf(x.y * scale);
    t.z = f2tf(x.z * scale); t.w = f2tf(x.w * scale);
    dst[i] = t;
}

// ===========================================================================
// GEMM body: C[M,N] = X[M,K] @ W[N,K]^T, K=N=1024. Inputs are tf32 bits.
// MODE 0: fp32 out + bias. MODE 1: tf32 [B,H,L,hd]. MODE 2: tf32 [B,H,hd,L].
// 128x128 CTA tile, 256 thr (8 warps 2x4), warp tile 64x32, K-chunk 32.
// 3-stage cp.async pipeline: each load gets ~2 compute phases of cover.
// ===========================================================================
#define GST (128 * 36)           // words per operand per stage
#define NSTG 3
#define GEMM_SMEM (NSTG * 2 * GST * 4)   // 110592 bytes

template<int MODE>
__device__ __forceinline__ void gemm_body(const uint32_t* __restrict__ X,
                                          const uint32_t* __restrict__ W,
                                          const float* __restrict__ bias,
                                          void* __restrict__ outv,
                                          uint32_t* dsm,
                                          int m0, int n0)
{
    const int tid  = threadIdx.x;
    const int wid  = tid >> 5, lane = tid & 31;
    const int qd   = lane & 3, gr = lane >> 2;
    const int wm   = wid >> 2, wn = wid & 3;

    float acc[4][4][4];
    #pragma unroll
    for (int a = 0; a < 4; a++)
        #pragma unroll
        for (int b = 0; b < 4; b++)
            #pragma unroll
            for (int c = 0; c < 4; c++) acc[a][b][c] = 0.f;

    const int lrow = tid >> 1;            // 0..127
    const int lcol = (tid & 1) * 16;      // 0 / 16
    const uint32_t* Xp = X + (size_t)(m0 + lrow) * D_ + lcol;
    const uint32_t* Wp = W + (size_t)(n0 + lrow) * D_ + lcol;
    const uint32_t sAb0 = smem_u32(dsm + lrow * 36 + lcol);

    const int a_r = ((lane >> 3) & 1) * 8 + (lane & 7);
    const int a_c = (lane >> 4) * 4;
    const int b_r = (lane >> 4) * 8 + (lane & 7);
    const int b_c = ((lane >> 3) & 1) * 4;
    const uint32_t sbase  = smem_u32(dsm);
    const uint32_t aAddr0 = sbase + (((wm * 64 + a_r) * 36 + a_c) << 2);
    const uint32_t bAddr0 = sbase + (GST << 2) + (((wn * 32 + b_r) * 36 + b_c) << 2);

    auto issue = [&](int c, int st) {
        const uint32_t sa = sAb0 + st * (2 * GST * 4);
        const uint32_t sb = sa + GST * 4;
        #pragma unroll
        for (int u = 0; u < 4; u++) {
            cp16(sa + u * 16, Xp + c + u * 4);
            cp16(sb + u * 16, Wp + c + u * 4);
        }
        asm volatile("cp.async.commit_group;");
    };

    issue(0, 0);
    issue(32, 1);

    int st = 0, st2 = 2;   // st = current compute stage; st2 = stage to fill
    for (int c = 0; c < D_; c += 32) {
        if (c + 32 < D_) asm volatile("cp.async.wait_group 1;");
        else             asm volatile("cp.async.wait_group 0;");
        __syncthreads();
        if (c + 64 < D_) issue(c + 64, st2);   // overlaps compute below

        const uint32_t soff = (uint32_t)st * (2 * GST * 4);
        #pragma unroll
        for (int kk = 0; kk < 32; kk += 8) {
            uint32_t af[4][4], bq[2][4];
            #pragma unroll
            for (int mt = 0; mt < 4; mt++)
                ldm4(af[mt], aAddr0 + soff + ((mt * 16 * 36 + kk) << 2));
            #pragma unroll
            for (int ntp = 0; ntp < 2; ntp++)
                ldm4(bq[ntp], bAddr0 + soff + ((ntp * 16 * 36 + kk) << 2));
            #pragma unroll
            for (int mt = 0; mt < 4; mt++)
                #pragma unroll
                for (int nt = 0; nt < 4; nt++)
                    mma8(acc[mt][nt], af[mt], &bq[nt >> 1][(nt & 1) * 2]);
        }
        st  = (st  == NSTG - 1) ? 0 : st + 1;
        st2 = (st2 == NSTG - 1) ? 0 : st2 + 1;
    }

    #pragma unroll
    for (int mt = 0; mt < 4; mt++) {
        #pragma unroll
        for (int half = 0; half < 2; half++) {
            const int m = m0 + wm * 64 + mt * 16 + gr + half * 8;
            #pragma unroll
            for (int nt = 0; nt < 4; nt++) {
                const int n = n0 + wn * 32 + nt * 8 + qd * 2;
                float2 v;
                v.x = acc[mt][nt][half * 2 + 0];
                v.y = acc[mt][nt][half * 2 + 1];
                if (MODE == 1) {
                    const int b = m / L_, l = m % L_, h = n / HD_, d = n % HD_;
                    uint2 t;
                    t.x = f2tf(v.x);
                    t.y = f2tf(v.y);
                    uint32_t* o = (uint32_t*)outv;
                    *(uint2*)&o[(((size_t)(b * H_ + h)) * L_ + l) * HD_ + d] = t;
                } else if (MODE == 2) {
                    const int b = m / L_, l = m % L_, h = n / HD_, d = n % HD_;
                    uint32_t* o = (uint32_t*)outv;
                    const size_t base = (((size_t)(b * H_ + h)) * HD_ + d) * L_ + l;
                    o[base]      = f2tf(v.x);
                    o[base + L_] = f2tf(v.y);
                } else {
                    v.x += bias[n]; v.y += bias[n + 1];
                    float* o = (float*)outv;
                    *(float2*)&o[(size_t)m * D_ + n] = v;
                }
            }
        }
    }
}

// Merged Q/K/V projection: blockIdx.z selects the problem.
__global__ __launch_bounds__(256, 2) void gemm_qkv(const uint32_t* __restrict__ xq,
                                                   const uint32_t* __restrict__ xk,
                                                   const uint32_t* __restrict__ xv,
                                                   const uint32_t* __restrict__ wq,
                                                   const uint32_t* __restrict__ wk,
                                                   const uint32_t* __restrict__ wv,
                                                   uint32_t* __restrict__ oq,
                                                   uint32_t* __restrict__ ok,
                                                   uint32_t* __restrict__ ov)
{
    extern __shared__ uint32_t dsm[];
    if (blockIdx.z == 0)
        gemm_body<1>(xq, wq, nullptr, oq, dsm, blockIdx.y * 128, blockIdx.x * 128);
    else if (blockIdx.z == 1)
        gemm_body<1>(xk, wk, nullptr, ok, dsm, blockIdx.y * 128, blockIdx.x * 128);
    else
        gemm_body<2>(xv, wv, nullptr, ov, dsm, blockIdx.y * 128, blockIdx.x * 128);
}

__global__ __launch_bounds__(256, 2) void gemm_out(const uint32_t* __restrict__ X,
                                                   const uint32_t* __restrict__ W,
                                                   const float* __restrict__ bias,
                                                   float* __restrict__ out)
{
    extern __shared__ uint32_t dsm[];
    gemm_body<0>(X, W, bias, out, dsm, blockIdx.y * 128, blockIdx.x * 128);
}

// ===========================================================================
// Flash attention: q-tile 128, 8 warps x 16 rows, tf32-bit inputs.
// Scores arrive in exp2 domain (log2e folded into Wq) -> raw ex2.approx.
// V pre-transposed [bh][dim][key] -> ldmatrix B-frags like K.
// smem: Qs 128x68, 2 stages of {K 64x68, Vt 64x68, msk 64}.
// ===========================================================================
#define FQW (128 * 68)
#define FKW (64 * 68)
#define FVW (64 * 68)
#define FSTG (FKW + FVW + 64)             // 8768 words per stage
#define FA_SMEM ((FQW + 2 * FSTG) * 4)    // 104960 bytes

__global__ __launch_bounds__(256, 2) void flash_attn(const uint32_t* __restrict__ q,
                                                     const uint32_t* __restrict__ k,
                                                     const uint32_t* __restrict__ vt,
                                                     const int*      __restrict__ mask,
                                                     uint32_t*       __restrict__ ctx)
{
    extern __shared__ uint32_t smu[];
    uint32_t* Qs = smu;

    const int bh = blockIdx.x;
    const int b  = bh / H_;
    const int h  = bh % H_;
    const int q0 = blockIdx.y * 128;
    const int tid  = threadIdx.x;
    const int wid  = tid >> 5, lane = tid & 31;
    const int qd   = lane & 3, gr = lane >> 2;

    const uint32_t* qbase  = q  + (size_t)bh * L_ * HD_;
    const uint32_t* kbase  = k  + (size_t)bh * L_ * HD_;
    const uint32_t* vtbase = vt + (size_t)bh * HD_ * L_;

    // Q tile: 128 rows, 256 threads -> 2 threads/row, 8 cp16 each
    {
        const int qr = tid >> 1, qc = (tid & 1) * 32;
        const uint32_t* src = qbase + (size_t)(q0 + qr) * HD_ + qc;
        const uint32_t dst = smem_u32(Qs + qr * 68 + qc);
        #pragma unroll
        for (int u = 0; u < 8; u++) cp16(dst + u * 16, src + u * 4);
    }

    // KV stage: 64 rows each, 256 threads -> 4 threads/row, 4 cp16 each.
    const int kvr = tid >> 2, kvc = (tid & 3) * 16;
    auto issueKV = [&](int k0, int s) {
        const uint32_t base = smem_u32(smu) + (FQW + s * FSTG) * 4;
        const uint32_t* ks = kbase  + (size_t)(k0 + kvr) * HD_ + kvc;
        const uint32_t* vs = vtbase + (size_t)kvr * L_ + k0 + kvc;
        const uint32_t kd = base + ((kvr * 68 + kvc) << 2);
        const uint32_t vd = base + ((FKW + kvr * 68 + kvc) << 2);
        #pragma unroll
        for (int u = 0; u < 4; u++) {
            cp16(kd + u * 16, ks + u * 4);
            cp16(vd + u * 16, vs + u * 4);
        }
        if (tid < 16)
            cp16(base + ((FKW + FVW) << 2) + tid * 16, mask + b * L_ + k0 + tid * 4);
        asm volatile("cp.async.commit_group;");
    };

    issueKV(0, 0);

    float accO[8][4];
    #pragma unroll
    for (int a = 0; a < 8; a++)
        #pragma unroll
        for (int c = 0; c < 4; c++) accO[a][c] = 0.f;
    float m_r0 = -1e30f, m_r1 = -1e30f, l_r0 = 0.f, l_r1 = 0.f;

    // ldmatrix lane addressing
    const int a_r = ((lane >> 3) & 1) * 8 + (lane & 7);
    const int a_c = (lane >> 4) * 4;
    const int k_r = (lane >> 4) * 8 + (lane & 7);
    const int k_c = ((lane >> 3) & 1) * 4;
    const uint32_t qAddr = smem_u32(Qs + (wid * 16 + a_r) * 68 + a_c);

    const int srcA = (lane & ~3) | (qd >> 1);
    const int srcB = srcA + 2;
    const bool odd = (qd & 1);

    for (int k0 = 0, st = 0; k0 < L_; k0 += 64, st ^= 1) {
        asm volatile("cp.async.wait_group 0;");
        __syncthreads();
        if (k0 + 64 < L_) issueKV(k0 + 64, st ^ 1);   // overlaps compute

        const uint32_t sbase = smem_u32(smu) + (FQW + st * FSTG) * 4;
        const uint32_t kAddr = sbase + ((k_r * 68 + k_c) << 2);
        const uint32_t vAddr = sbase + (FKW << 2) + ((k_r * 68 + k_c) << 2);
        const int* mskp = (const int*)(smu + FQW + st * FSTG + FKW + FVW);

        // ---- S = Q*K^T (in exp2 domain: log2e/8 folded into Wq)
        float sacc[8][4];
        #pragma unroll
        for (int a = 0; a < 8; a++)
            #pragma unroll
            for (int c = 0; c < 4; c++) sacc[a][c] = 0.f;

        #pragma unroll
        for (int g = 0; g < 8; g++) {
            uint32_t aq[4], kb[4][4];
            ldm4(aq, qAddr + ((g * 8) << 2));
            #pragma unroll
            for (int ntp = 0; ntp < 4; ntp++)
                ldm4(kb[ntp], kAddr + ((ntp * 16 * 68 + g * 8) << 2));
            #pragma unroll
            for (int nt = 0; nt < 8; nt++)
                mma8(sacc[nt], aq, &kb[nt >> 1][(nt & 1) * 2]);
        }

        // ---- mask + online softmax in registers (exp2 domain)
        #pragma unroll
        for (int nt = 0; nt < 8; nt++) {
            if (!mskp[8 * nt + 2 * qd])     { sacc[nt][0] = -1e30f; sacc[nt][2] = -1e30f; }
            if (!mskp[8 * nt + 2 * qd + 1]) { sacc[nt][1] = -1e30f; sacc[nt][3] = -1e30f; }
        }
        float rm0 = m_r0, rm1 = m_r1;
        #pragma unroll
        for (int nt = 0; nt < 8; nt++) {
            rm0 = fmaxf(rm0, fmaxf(sacc[nt][0], sacc[nt][1]));
            rm1 = fmaxf(rm1, fmaxf(sacc[nt][2], sacc[nt][3]));
        }
        rm0 = fmaxf(rm0, __shfl_xor_sync(0xFFFFFFFF, rm0, 1));
        rm0 = fmaxf(rm0, __shfl_xor_sync(0xFFFFFFFF, rm0, 2));
        rm1 = fmaxf(rm1, __shfl_xor_sync(0xFFFFFFFF, rm1, 1));
        rm1 = fmaxf(rm1, __shfl_xor_sync(0xFFFFFFFF, rm1, 2));

        const float corr0 = ex2(m_r0 - rm0);
        const float corr1 = ex2(m_r1 - rm1);
        float ls0 = 0.f, ls1 = 0.f;
        #pragma unroll
        for (int nt = 0; nt < 8; nt++) {
            sacc[nt][0] = (sacc[nt][0] < -1e29f) ? 0.f : ex2(sacc[nt][0] - rm0);
            sacc[nt][1] = (sacc[nt][1] < -1e29f) ? 0.f : ex2(sacc[nt][1] - rm0);
            sacc[nt][2] = (sacc[nt][2] < -1e29f) ? 0.f : ex2(sacc[nt][2] - rm1);
            sacc[nt][3] = (sacc[nt][3] < -1e29f) ? 0.f : ex2(sacc[nt][3] - rm1);
            ls0 += sacc[nt][0] + sacc[nt][1];
            ls1 += sacc[nt][2] + sacc[nt][3];
        }
        ls0 += __shfl_xor_sync(0xFFFFFFFF, ls0, 1);
        ls0 += __shfl_xor_sync(0xFFFFFFFF, ls0, 2);
        ls1 += __shfl_xor_sync(0xFFFFFFFF, ls1, 1);
        ls1 += __shfl_xor_sync(0xFFFFFFFF, ls1, 2);

        m_r0 = rm0; m_r1 = rm1;
        l_r0 = l_r0 * corr0 + ls0;
        l_r1 = l_r1 * corr1 + ls1;

        #pragma unroll
        for (int nt = 0; nt < 8; nt++) {
            accO[nt][0] *= corr0; accO[nt][1] *= corr0;
            accO[nt][2] *= corr1; accO[nt][3] *= corr1;
        }

        // ---- P (C-frag) -> A-frag via quad shuffles, then O += P @ Vt
        #pragma unroll
        for (int g = 0; g < 8; g++) {
            const float v0 = __shfl_sync(0xFFFFFFFF, sacc[g][0], srcA);
            const float v1 = __shfl_sync(0xFFFFFFFF, sacc[g][1], srcA);
            const float v2 = __shfl_sync(0xFFFFFFFF, sacc[g][2], srcA);
            const float v3 = __shfl_sync(0xFFFFFFFF, sacc[g][3], srcA);
            const float w0 = __shfl_sync(0xFFFFFFFF, sacc[g][0], srcB);
            const float w1 = __shfl_sync(0xFFFFFFFF, sacc[g][1], srcB);
            const float w2 = __shfl_sync(0xFFFFFFFF, sacc[g][2], srcB);
            const float w3 = __shfl_sync(0xFFFFFFFF, sacc[g][3], srcB);
            uint32_t pa[4];
            pa[0] = f2tf(odd ? v1 : v0);
            pa[1] = f2tf(odd ? v3 : v2);
            pa[2] = f2tf(odd ? w1 : w0);
            pa[3] = f2tf(odd ? w3 : w2);
            uint32_t vb[4][4];
            #pragma unroll
            for (int ntp = 0; ntp < 4; ntp++)
                ldm4(vb[ntp], vAddr + ((ntp * 16 * 68 + g * 8) << 2));
            #pragma unroll
            for (int nt = 0; nt < 8; nt++)
                mma8(accO[nt], pa, &vb[nt >> 1][(nt & 1) * 2]);
        }
    }

    // ---- normalize + write ctx as tf32 bits (combined-head layout)
    {
        const float i0 = (l_r0 > 0.f) ? 1.f / l_r0 : 0.f;
        const float i1 = (l_r1 > 0.f) ? 1.f / l_r1 : 0.f;
        const int row0 = q0 + wid * 16 + gr;
        #pragma unroll
        for (int nt = 0; nt < 8; nt++) {
            const int n = h * HD_ + nt * 8 + qd * 2;
            uint2 o0, o1;
            o0.x = f2tf(accO[nt][0] * i0); o0.y = f2tf(accO[nt][1] * i0);
            o1.x = f2tf(accO[nt][2] * i1); o1.y = f2tf(accO[nt][3] * i1);
            *(uint2*)&ctx[((size_t)(b * L_ + row0)) * D_ + n] = o0;
            *(uint2*)&ctx[((size_t)(b * L_ + row0 + 8)) * D_ + n] = o1;
        }
    }
}

// ---------------------------------------------------------------------------
extern "C" void kernel_launch(void* const* d_in, const int* in_sizes, int n_in,
                              void* d_out, int out_size)
{
    const float* query = (const float*)d_in[0];
    const float* key_  = (const float*)d_in[1];
    const float* value = (const float*)d_in[2];
    const int*   mask  = (const int*)  d_in[3];
    const float* Wq    = (const float*)d_in[4];
    const float* Wk    = (const float*)d_in[5];
    const float* Wv    = (const float*)d_in[6];
    const float* Wo    = (const float*)d_in[7];
    const float* bo    = (const float*)d_in[8];
    float* out = (float*)d_out;

    uint32_t *xq, *xk, *xv, *wq, *wk, *wv, *wo, *pq, *pk, *pv, *pc;
    cudaGetSymbolAddress((void**)&xq, g_xq);
    cudaGetSymbolAddress((void**)&xk, g_xk);
    cudaGetSymbolAddress((void**)&xv, g_xv);
    cudaGetSymbolAddress((void**)&wq, g_wq);
    cudaGetSymbolAddress((void**)&wk, g_wk);
    cudaGetSymbolAddress((void**)&wv, g_wv);
    cudaGetSymbolAddress((void**)&wo, g_wo);
    cudaGetSymbolAddress((void**)&pq, g_q);
    cudaGetSymbolAddress((void**)&pk, g_k);
    cudaGetSymbolAddress((void**)&pv, g_v);
    cudaGetSymbolAddress((void**)&pc, g_ctx);

    cudaFuncSetAttribute(gemm_qkv,
                         cudaFuncAttributeMaxDynamicSharedMemorySize, GEMM_SMEM);
    cudaFuncSetAttribute(gemm_out,
                         cudaFuncAttributeMaxDynamicSharedMemorySize, GEMM_SMEM);
    cudaFuncSetAttribute(flash_attn,
                         cudaFuncAttributeMaxDynamicSharedMemorySize, FA_SMEM);

    cvt_all<<<NCVT / 256, 256>>>((const float4*)query, (const float4*)key_,
                                 (const float4*)value, (const float4*)Wq,
                                 (const float4*)Wk, (const float4*)Wv,
                                 (const float4*)Wo,
                                 (uint4*)xq, (uint4*)xk, (uint4*)xv,
                                 (uint4*)wq, (uint4*)wk, (uint4*)wv, (uint4*)wo);

    gemm_qkv<<<dim3(D_ / 128, M_ / 128, 3), 256, GEMM_SMEM>>>(
        xq, xk, xv, wq, wk, wv, pq, pk, pv);

    flash_attn<<<dim3(B_ * H_, L_ / 128), 256, FA_SMEM>>>(pq, pk, pv, mask, pc);

    gemm_out<<<dim3(D_ / 128, M_ / 128), 256, GEMM_SMEM>>>(pc, wo, bo, out);
}